// round 2
// baseline (speedup 1.0000x reference)
#include <cuda_runtime.h>
#include <math.h>

#define DIM 768
#define BATCH 16
#define SEQ 1024
#define ROWS (BATCH*SEQ)   // 16384

// ---------------- scratch (allocated at module load, legal) ----------------
__device__ float g_Q[(size_t)ROWS*DIM];
__device__ float g_KA[(size_t)ROWS*DIM];
__device__ float g_KB[(size_t)ROWS*DIM];
__device__ float g_VA[(size_t)ROWS*DIM];
__device__ float g_VB[(size_t)ROWS*DIM];
__device__ float g_interp[(size_t)ROWS*DIM];
__device__ float g_h[(size_t)ROWS*DIM];
__device__ float g_scores[(size_t)BATCH*SEQ*SEQ];

// ---------------- GEMM: C = alpha * A @ op(B) (+ bias) (+ C) ----------------
// A: [M,K] row-major. TRANS_B: B is [N,K] row-major (C=A*B^T). !TRANS_B: B is [K,N].
constexpr int BM = 128, BN = 128, BK = 16;

template<bool TRANS_B, bool ADD_C, bool HAS_BIAS>
__global__ __launch_bounds__(256)
void gemm_kernel(const float* __restrict__ Ag, const float* __restrict__ Bg,
                 const float* __restrict__ bias, float* __restrict__ Cg,
                 int M, int N, int K, long sA, long sB, long sC, float alpha)
{
    const float* A = Ag + (size_t)blockIdx.z * sA;
    const float* B = Bg + (size_t)blockIdx.z * sB;
    float*       C = Cg + (size_t)blockIdx.z * sC;

    __shared__ float As[BK][BM];
    __shared__ float Bs[BK][BN];

    const int tid = threadIdx.x;
    const int tx  = tid & 15;   // n-dir
    const int ty  = tid >> 4;   // m-dir

    const int m0 = blockIdx.y * BM;
    const int n0 = blockIdx.x * BN;

    float acc[8][8] = {};

    for (int kk = 0; kk < K; kk += BK) {
        // load A tile (128x16) as float4, store transposed As[k][m]
        #pragma unroll
        for (int i = 0; i < 2; i++) {
            int e = tid + i * 256;
            int r = e >> 2;     // 0..127
            int c = e & 3;      // 0..3
            float4 v = *reinterpret_cast<const float4*>(&A[(size_t)(m0 + r) * K + kk + c * 4]);
            As[c*4+0][r] = v.x; As[c*4+1][r] = v.y;
            As[c*4+2][r] = v.z; As[c*4+3][r] = v.w;
        }
        if (TRANS_B) {
            #pragma unroll
            for (int i = 0; i < 2; i++) {
                int e = tid + i * 256;
                int r = e >> 2;
                int c = e & 3;
                float4 v = *reinterpret_cast<const float4*>(&B[(size_t)(n0 + r) * K + kk + c * 4]);
                Bs[c*4+0][r] = v.x; Bs[c*4+1][r] = v.y;
                Bs[c*4+2][r] = v.z; Bs[c*4+3][r] = v.w;
            }
        } else {
            #pragma unroll
            for (int i = 0; i < 2; i++) {
                int e = tid + i * 256;
                int r = e >> 5;     // 0..15 (k)
                int c = e & 31;     // 0..31 (n/4)
                float4 v = *reinterpret_cast<const float4*>(&B[(size_t)(kk + r) * N + n0 + c * 4]);
                *reinterpret_cast<float4*>(&Bs[r][c*4]) = v;
            }
        }
        __syncthreads();

        #pragma unroll
        for (int k = 0; k < BK; k++) {
            float ra[8], rb[8];
            *reinterpret_cast<float4*>(&ra[0]) = *reinterpret_cast<const float4*>(&As[k][ty*8]);
            *reinterpret_cast<float4*>(&ra[4]) = *reinterpret_cast<const float4*>(&As[k][ty*8+4]);
            *reinterpret_cast<float4*>(&rb[0]) = *reinterpret_cast<const float4*>(&Bs[k][tx*8]);
            *reinterpret_cast<float4*>(&rb[4]) = *reinterpret_cast<const float4*>(&Bs[k][tx*8+4]);
            #pragma unroll
            for (int i = 0; i < 8; i++)
                #pragma unroll
                for (int j = 0; j < 8; j++)
                    acc[i][j] = fmaf(ra[i], rb[j], acc[i][j]);
        }
        __syncthreads();
    }

    #pragma unroll
    for (int i = 0; i < 8; i++) {
        int row = m0 + ty * 8 + i;
        #pragma unroll
        for (int jj = 0; jj < 2; jj++) {
            int col = n0 + tx * 8 + jj * 4;
            float4 v;
            v.x = alpha * acc[i][jj*4+0];
            v.y = alpha * acc[i][jj*4+1];
            v.z = alpha * acc[i][jj*4+2];
            v.w = alpha * acc[i][jj*4+3];
            if (HAS_BIAS) {
                v.x += bias[col+0]; v.y += bias[col+1];
                v.z += bias[col+2]; v.w += bias[col+3];
            }
            float* cp = &C[(size_t)row * N + col];
            if (ADD_C) {
                float4 o = *reinterpret_cast<const float4*>(cp);
                v.x += o.x; v.y += o.y; v.z += o.z; v.w += o.w;
            }
            *reinterpret_cast<float4*>(cp) = v;
        }
    }
}

// ---------------- row softmax over SEQ=1024 (one block / row) ----------------
__global__ __launch_bounds__(256)
void softmax_kernel(float* __restrict__ S)
{
    __shared__ float sh[8];
    float* p = S + (size_t)blockIdx.x * SEQ;
    const int t = threadIdx.x;
    float4 v = reinterpret_cast<float4*>(p)[t];

    float m = fmaxf(fmaxf(v.x, v.y), fmaxf(v.z, v.w));
    #pragma unroll
    for (int o = 16; o > 0; o >>= 1) m = fmaxf(m, __shfl_xor_sync(0xffffffffu, m, o));
    if ((t & 31) == 0) sh[t >> 5] = m;
    __syncthreads();
    m = sh[0];
    #pragma unroll
    for (int i = 1; i < 8; i++) m = fmaxf(m, sh[i]);
    __syncthreads();

    v.x = expf(v.x - m); v.y = expf(v.y - m);
    v.z = expf(v.z - m); v.w = expf(v.w - m);
    float s = v.x + v.y + v.z + v.w;
    #pragma unroll
    for (int o = 16; o > 0; o >>= 1) s += __shfl_xor_sync(0xffffffffu, s, o);
    if ((t & 31) == 0) sh[t >> 5] = s;
    __syncthreads();
    s = sh[0];
    #pragma unroll
    for (int i = 1; i < 8; i++) s += sh[i];

    float inv = 1.0f / s;
    v.x *= inv; v.y *= inv; v.z *= inv; v.w *= inv;
    reinterpret_cast<float4*>(p)[t] = v;
}

// ------------- fused residual-add + LayerNorm over DIM=768 (one block / row) -------------
__global__ __launch_bounds__(256)
void ln_kernel(const float* __restrict__ interp, const float* __restrict__ xC,
               const float* __restrict__ gamma, const float* __restrict__ beta,
               float* __restrict__ H)
{
    __shared__ float sh[8];
    const size_t row = blockIdx.x;
    const float* a = interp + row * DIM;
    const float* c = xC + row * DIM;
    const int t = threadIdx.x;

    float x0 = a[t]       + c[t];
    float x1 = a[t + 256] + c[t + 256];
    float x2 = a[t + 512] + c[t + 512];

    float s = x0 + x1 + x2;
    #pragma unroll
    for (int o = 16; o > 0; o >>= 1) s += __shfl_xor_sync(0xffffffffu, s, o);
    if ((t & 31) == 0) sh[t >> 5] = s;
    __syncthreads();
    s = sh[0];
    #pragma unroll
    for (int i = 1; i < 8; i++) s += sh[i];
    const float mu = s * (1.0f / DIM);
    __syncthreads();

    float d0 = x0 - mu, d1 = x1 - mu, d2 = x2 - mu;
    float q = d0*d0 + d1*d1 + d2*d2;
    #pragma unroll
    for (int o = 16; o > 0; o >>= 1) q += __shfl_xor_sync(0xffffffffu, q, o);
    if ((t & 31) == 0) sh[t >> 5] = q;
    __syncthreads();
    q = sh[0];
    #pragma unroll
    for (int i = 1; i < 8; i++) q += sh[i];

    const float rstd = rsqrtf(q * (1.0f / DIM) + 1e-5f);
    float* hp = H + row * DIM;
    hp[t]       = d0 * rstd * gamma[t]       + beta[t];
    hp[t + 256] = d1 * rstd * gamma[t + 256] + beta[t + 256];
    hp[t + 512] = d2 * rstd * gamma[t + 512] + beta[t + 512];
}

// ---------------------------------- launch ----------------------------------
extern "C" void kernel_launch(void* const* d_in, const int* in_sizes, int n_in,
                              void* d_out, int out_size)
{
    const float* xA    = (const float*)d_in[0];
    const float* xB    = (const float*)d_in[1];
    const float* xC    = (const float*)d_in[2];
    const float* Wq    = (const float*)d_in[3];
    const float* bq    = (const float*)d_in[4];
    const float* Wk    = (const float*)d_in[5];
    const float* bk    = (const float*)d_in[6];
    const float* Wv    = (const float*)d_in[7];
    const float* bv    = (const float*)d_in[8];
    const float* gamma = (const float*)d_in[9];
    const float* beta  = (const float*)d_in[10];
    const float* Wfc   = (const float*)d_in[11];
    const float* bfc   = (const float*)d_in[12];
    float* out = (float*)d_out;

    float *Q, *KA, *KB, *VA, *VB, *interp, *h, *scores;
    cudaGetSymbolAddress((void**)&Q,      g_Q);
    cudaGetSymbolAddress((void**)&KA,     g_KA);
    cudaGetSymbolAddress((void**)&KB,     g_KB);
    cudaGetSymbolAddress((void**)&VA,     g_VA);
    cudaGetSymbolAddress((void**)&VB,     g_VB);
    cudaGetSymbolAddress((void**)&interp, g_interp);
    cudaGetSymbolAddress((void**)&h,      g_h);
    cudaGetSymbolAddress((void**)&scores, g_scores);

    const dim3 blk(256);
    const dim3 gProj(DIM / BN, ROWS / BM, 1);      // (6,128)
    const dim3 gScore(SEQ / BN, SEQ / BM, BATCH);  // (8,8,16)
    const dim3 gAV(DIM / BN, SEQ / BM, BATCH);     // (6,8,16)
    const long sQK = (long)SEQ * DIM;
    const long sS  = (long)SEQ * SEQ;
    const float scale = 1.0f / sqrtf((float)DIM);

    // projections
    gemm_kernel<true,false,true><<<gProj, blk>>>(xC, Wq, bq, Q,  ROWS, DIM, DIM, 0,0,0, 1.0f);
    gemm_kernel<true,false,true><<<gProj, blk>>>(xA, Wk, bk, KA, ROWS, DIM, DIM, 0,0,0, 1.0f);
    gemm_kernel<true,false,true><<<gProj, blk>>>(xB, Wk, bk, KB, ROWS, DIM, DIM, 0,0,0, 1.0f);
    gemm_kernel<true,false,true><<<gProj, blk>>>(xA, Wv, bv, VA, ROWS, DIM, DIM, 0,0,0, 1.0f);
    gemm_kernel<true,false,true><<<gProj, blk>>>(xB, Wv, bv, VB, ROWS, DIM, DIM, 0,0,0, 1.0f);

    // attention A
    gemm_kernel<true,false,false><<<gScore, blk>>>(Q, KA, nullptr, scores, SEQ, SEQ, DIM, sQK, sQK, sS, scale);
    softmax_kernel<<<ROWS, blk>>>(scores);
    gemm_kernel<false,false,false><<<gAV, blk>>>(scores, VA, nullptr, interp, SEQ, DIM, SEQ, sS, sQK, sQK, 1.0f);

    // attention B (accumulate)
    gemm_kernel<true,false,false><<<gScore, blk>>>(Q, KB, nullptr, scores, SEQ, SEQ, DIM, sQK, sQK, sS, scale);
    softmax_kernel<<<ROWS, blk>>>(scores);
    gemm_kernel<false,true,false><<<gAV, blk>>>(scores, VB, nullptr, interp, SEQ, DIM, SEQ, sS, sQK, sQK, 1.0f);

    // residual + LN, then FC
    ln_kernel<<<ROWS, blk>>>(interp, xC, gamma, beta, h);
    gemm_kernel<true,false,true><<<gProj, blk>>>(h, Wfc, bfc, out, ROWS, DIM, DIM, 0,0,0, 1.0f);
}

// round 3
// speedup vs baseline: 2.9865x; 2.9865x over previous
#include <cuda_runtime.h>
#include <math.h>
#include <stdint.h>

#define DIM 768
#define BATCH 16
#define SEQ 1024
#define ROWS (BATCH*SEQ)   // 16384

// ---------------- scratch (allocated at module load, legal) ----------------
__device__ float g_Q[(size_t)ROWS*DIM];
__device__ float g_KA[(size_t)ROWS*DIM];
__device__ float g_KB[(size_t)ROWS*DIM];
__device__ float g_VA[(size_t)ROWS*DIM];
__device__ float g_VB[(size_t)ROWS*DIM];
__device__ float g_interp[(size_t)ROWS*DIM];
__device__ float g_h[(size_t)ROWS*DIM];
__device__ float g_scores[(size_t)BATCH*SEQ*SEQ];

// ---------------- tf32 tensor-core GEMM ----------------
// C = alpha * A @ op(B) (+bias) (+C).  A:[M,K] row-major.
// TRANS_B: B:[N,K] row-major (C=A*B^T).  !TRANS_B: B:[K,N] row-major.
constexpr int BM = 128, BN = 128, BK = 32;
constexpr int LDS_S = BK + 4;                 // 36-float smem row stride
constexpr int ASZ = BM * LDS_S;               // floats
constexpr int BSZ = BN * LDS_S;
constexpr int STAGEF = ASZ + BSZ;             // floats per stage
constexpr int SMEM_BYTES = 2 * STAGEF * 4;    // 73728 bytes

__device__ __forceinline__ uint32_t f2tf(float x) {
    uint32_t u;
    asm("cvt.rna.tf32.f32 %0, %1;" : "=r"(u) : "f"(x));
    return u;
}
__device__ __forceinline__ void cp16(uint32_t d, const float* s) {
    asm volatile("cp.async.ca.shared.global [%0], [%1], 16;" :: "r"(d), "l"(s));
}
__device__ __forceinline__ void cp4(uint32_t d, const float* s) {
    asm volatile("cp.async.ca.shared.global [%0], [%1], 4;" :: "r"(d), "l"(s));
}
__device__ __forceinline__ void mma_tf32(float* c, const uint32_t* a, const uint32_t* b) {
    asm("mma.sync.aligned.m16n8k8.row.col.f32.tf32.tf32.f32 "
        "{%0,%1,%2,%3}, {%4,%5,%6,%7}, {%8,%9}, {%0,%1,%2,%3};"
        : "+f"(c[0]), "+f"(c[1]), "+f"(c[2]), "+f"(c[3])
        : "r"(a[0]), "r"(a[1]), "r"(a[2]), "r"(a[3]), "r"(b[0]), "r"(b[1]));
}

template<bool TRANS_B, bool ADD_C, bool HAS_BIAS>
__global__ __launch_bounds__(256)
void mma_gemm(const float* __restrict__ Ag, const float* __restrict__ Bg,
              const float* __restrict__ bias, float* __restrict__ Cg,
              int M, int N, int K, long sA, long sB, long sC, float alpha)
{
    extern __shared__ float sm[];
    const float* A = Ag + (size_t)blockIdx.z * sA;
    const float* B = Bg + (size_t)blockIdx.z * sB;
    float*       C = Cg + (size_t)blockIdx.z * sC;

    const int t    = threadIdx.x;
    const int lane = t & 31;
    const int warp = t >> 5;
    const int wm   = warp >> 1;      // 0..3
    const int wn   = warp & 1;       // 0..1
    const int g    = lane >> 2;      // 0..7
    const int c    = lane & 3;       // 0..3
    const int m0   = blockIdx.y * BM;
    const int n0   = blockIdx.x * BN;

    const uint32_t smBase = (uint32_t)__cvta_generic_to_shared(sm);

    float acc[2][8][4] = {};

    const int nkt = K / BK;

    auto issue = [&](int kt, int st) {
        const float* Ab = A + (size_t)m0 * K + kt * BK;
        uint32_t as = smBase + st * STAGEF * 4;
        #pragma unroll
        for (int i = 0; i < 4; i++) {
            int idx = t + 256 * i;
            int r = idx >> 3, kq = idx & 7;
            cp16(as + (uint32_t)(r * LDS_S + kq * 4) * 4, Ab + (size_t)r * K + kq * 4);
        }
        uint32_t bs = smBase + (st * STAGEF + ASZ) * 4;
        if (TRANS_B) {
            const float* Bb = B + (size_t)n0 * K + kt * BK;
            #pragma unroll
            for (int i = 0; i < 4; i++) {
                int idx = t + 256 * i;
                int r = idx >> 3, kq = idx & 7;
                cp16(bs + (uint32_t)(r * LDS_S + kq * 4) * 4, Bb + (size_t)r * K + kq * 4);
            }
        } else {
            const float* Bb = B + (size_t)(kt * BK) * N + n0;
            #pragma unroll
            for (int i = 0; i < 16; i++) {
                int idx = t + 256 * i;
                int nq = idx & 127, kr = idx >> 7;
                cp4(bs + (uint32_t)(nq * LDS_S + kr) * 4, Bb + (size_t)kr * N + nq);
            }
        }
        asm volatile("cp.async.commit_group;");
    };

    issue(0, 0);
    int st = 0;
    for (int kt = 0; kt < nkt; kt++) {
        if (kt + 1 < nkt) {
            issue(kt + 1, st ^ 1);
            asm volatile("cp.async.wait_group 1;");
        } else {
            asm volatile("cp.async.wait_group 0;");
        }
        __syncthreads();

        const float* As = sm + st * STAGEF;
        const float* Bs = As + ASZ;
        const float* aP = As + (wm * 32 + g) * LDS_S + c;
        const float* bP = Bs + (wn * 64 + g) * LDS_S + c;

        #pragma unroll
        for (int ks = 0; ks < 4; ks++) {
            uint32_t af[2][4];
            #pragma unroll
            for (int mi = 0; mi < 2; mi++) {
                const float* p = aP + mi * 16 * LDS_S + ks * 8;
                af[mi][0] = f2tf(p[0]);
                af[mi][1] = f2tf(p[8 * LDS_S]);
                af[mi][2] = f2tf(p[4]);
                af[mi][3] = f2tf(p[8 * LDS_S + 4]);
            }
            uint32_t bf[8][2];
            #pragma unroll
            for (int ni = 0; ni < 8; ni++) {
                const float* p = bP + ni * 8 * LDS_S + ks * 8;
                bf[ni][0] = f2tf(p[0]);
                bf[ni][1] = f2tf(p[4]);
            }
            #pragma unroll
            for (int mi = 0; mi < 2; mi++)
                #pragma unroll
                for (int ni = 0; ni < 8; ni++)
                    mma_tf32(acc[mi][ni], af[mi], bf[ni]);
        }
        __syncthreads();
        st ^= 1;
    }

    // epilogue
    #pragma unroll
    for (int mi = 0; mi < 2; mi++) {
        int r0 = m0 + wm * 32 + mi * 16 + g;
        int r1 = r0 + 8;
        #pragma unroll
        for (int ni = 0; ni < 8; ni++) {
            int col = n0 + wn * 64 + ni * 8 + 2 * c;
            float2 v0, v1;
            v0.x = alpha * acc[mi][ni][0];
            v0.y = alpha * acc[mi][ni][1];
            v1.x = alpha * acc[mi][ni][2];
            v1.y = alpha * acc[mi][ni][3];
            if (HAS_BIAS) {
                float bx = bias[col], by = bias[col + 1];
                v0.x += bx; v0.y += by;
                v1.x += bx; v1.y += by;
            }
            float* p0 = &C[(size_t)r0 * N + col];
            float* p1 = &C[(size_t)r1 * N + col];
            if (ADD_C) {
                float2 o0 = *reinterpret_cast<const float2*>(p0);
                float2 o1 = *reinterpret_cast<const float2*>(p1);
                v0.x += o0.x; v0.y += o0.y;
                v1.x += o1.x; v1.y += o1.y;
            }
            *reinterpret_cast<float2*>(p0) = v0;
            *reinterpret_cast<float2*>(p1) = v1;
        }
    }
}

// ---------------- row softmax over SEQ=1024 (one block / row) ----------------
__global__ __launch_bounds__(256)
void softmax_kernel(float* __restrict__ S)
{
    __shared__ float sh[8];
    float* p = S + (size_t)blockIdx.x * SEQ;
    const int t = threadIdx.x;
    float4 v = reinterpret_cast<float4*>(p)[t];

    float m = fmaxf(fmaxf(v.x, v.y), fmaxf(v.z, v.w));
    #pragma unroll
    for (int o = 16; o > 0; o >>= 1) m = fmaxf(m, __shfl_xor_sync(0xffffffffu, m, o));
    if ((t & 31) == 0) sh[t >> 5] = m;
    __syncthreads();
    m = sh[0];
    #pragma unroll
    for (int i = 1; i < 8; i++) m = fmaxf(m, sh[i]);
    __syncthreads();

    v.x = expf(v.x - m); v.y = expf(v.y - m);
    v.z = expf(v.z - m); v.w = expf(v.w - m);
    float s = v.x + v.y + v.z + v.w;
    #pragma unroll
    for (int o = 16; o > 0; o >>= 1) s += __shfl_xor_sync(0xffffffffu, s, o);
    if ((t & 31) == 0) sh[t >> 5] = s;
    __syncthreads();
    s = sh[0];
    #pragma unroll
    for (int i = 1; i < 8; i++) s += sh[i];

    float inv = 1.0f / s;
    v.x *= inv; v.y *= inv; v.z *= inv; v.w *= inv;
    reinterpret_cast<float4*>(p)[t] = v;
}

// ------------- fused residual-add + LayerNorm over DIM=768 -------------
__global__ __launch_bounds__(256)
void ln_kernel(const float* __restrict__ interp, const float* __restrict__ xC,
               const float* __restrict__ gamma, const float* __restrict__ beta,
               float* __restrict__ H)
{
    __shared__ float sh[8];
    const size_t row = blockIdx.x;
    const float* a = interp + row * DIM;
    const float* c = xC + row * DIM;
    const int t = threadIdx.x;

    float x0 = a[t]       + c[t];
    float x1 = a[t + 256] + c[t + 256];
    float x2 = a[t + 512] + c[t + 512];

    float s = x0 + x1 + x2;
    #pragma unroll
    for (int o = 16; o > 0; o >>= 1) s += __shfl_xor_sync(0xffffffffu, s, o);
    if ((t & 31) == 0) sh[t >> 5] = s;
    __syncthreads();
    s = sh[0];
    #pragma unroll
    for (int i = 1; i < 8; i++) s += sh[i];
    const float mu = s * (1.0f / DIM);
    __syncthreads();

    float d0 = x0 - mu, d1 = x1 - mu, d2 = x2 - mu;
    float q = d0*d0 + d1*d1 + d2*d2;
    #pragma unroll
    for (int o = 16; o > 0; o >>= 1) q += __shfl_xor_sync(0xffffffffu, q, o);
    if ((t & 31) == 0) sh[t >> 5] = q;
    __syncthreads();
    q = sh[0];
    #pragma unroll
    for (int i = 1; i < 8; i++) q += sh[i];

    const float rstd = rsqrtf(q * (1.0f / DIM) + 1e-5f);
    float* hp = H + row * DIM;
    hp[t]       = d0 * rstd * gamma[t]       + beta[t];
    hp[t + 256] = d1 * rstd * gamma[t + 256] + beta[t + 256];
    hp[t + 512] = d2 * rstd * gamma[t + 512] + beta[t + 512];
}

// ---------------------------------- launch ----------------------------------
extern "C" void kernel_launch(void* const* d_in, const int* in_sizes, int n_in,
                              void* d_out, int out_size)
{
    const float* xA    = (const float*)d_in[0];
    const float* xB    = (const float*)d_in[1];
    const float* xC    = (const float*)d_in[2];
    const float* Wq    = (const float*)d_in[3];
    const float* bq    = (const float*)d_in[4];
    const float* Wk    = (const float*)d_in[5];
    const float* bk    = (const float*)d_in[6];
    const float* Wv    = (const float*)d_in[7];
    const float* bv    = (const float*)d_in[8];
    const float* gamma = (const float*)d_in[9];
    const float* beta  = (const float*)d_in[10];
    const float* Wfc   = (const float*)d_in[11];
    const float* bfc   = (const float*)d_in[12];
    float* out = (float*)d_out;

    float *Q, *KA, *KB, *VA, *VB, *interp, *h, *scores;
    cudaGetSymbolAddress((void**)&Q,      g_Q);
    cudaGetSymbolAddress((void**)&KA,     g_KA);
    cudaGetSymbolAddress((void**)&KB,     g_KB);
    cudaGetSymbolAddress((void**)&VA,     g_VA);
    cudaGetSymbolAddress((void**)&VB,     g_VB);
    cudaGetSymbolAddress((void**)&interp, g_interp);
    cudaGetSymbolAddress((void**)&h,      g_h);
    cudaGetSymbolAddress((void**)&scores, g_scores);

    cudaFuncSetAttribute(mma_gemm<true,  false, true >, cudaFuncAttributeMaxDynamicSharedMemorySize, SMEM_BYTES);
    cudaFuncSetAttribute(mma_gemm<true,  false, false>, cudaFuncAttributeMaxDynamicSharedMemorySize, SMEM_BYTES);
    cudaFuncSetAttribute(mma_gemm<false, false, false>, cudaFuncAttributeMaxDynamicSharedMemorySize, SMEM_BYTES);
    cudaFuncSetAttribute(mma_gemm<false, true,  false>, cudaFuncAttributeMaxDynamicSharedMemorySize, SMEM_BYTES);

    const dim3 blk(256);
    const dim3 gProj(DIM / BN, ROWS / BM, 1);      // (6,128)
    const dim3 gScore(SEQ / BN, SEQ / BM, BATCH);  // (8,8,16)
    const dim3 gAV(DIM / BN, SEQ / BM, BATCH);     // (6,8,16)
    const long sQK = (long)SEQ * DIM;
    const long sS  = (long)SEQ * SEQ;
    const float scale = 1.0f / sqrtf((float)DIM);

    // projections
    mma_gemm<true,false,true><<<gProj, blk, SMEM_BYTES>>>(xC, Wq, bq, Q,  ROWS, DIM, DIM, 0,0,0, 1.0f);
    mma_gemm<true,false,true><<<gProj, blk, SMEM_BYTES>>>(xA, Wk, bk, KA, ROWS, DIM, DIM, 0,0,0, 1.0f);
    mma_gemm<true,false,true><<<gProj, blk, SMEM_BYTES>>>(xB, Wk, bk, KB, ROWS, DIM, DIM, 0,0,0, 1.0f);
    mma_gemm<true,false,true><<<gProj, blk, SMEM_BYTES>>>(xA, Wv, bv, VA, ROWS, DIM, DIM, 0,0,0, 1.0f);
    mma_gemm<true,false,true><<<gProj, blk, SMEM_BYTES>>>(xB, Wv, bv, VB, ROWS, DIM, DIM, 0,0,0, 1.0f);

    // attention A
    mma_gemm<true,false,false><<<gScore, blk, SMEM_BYTES>>>(Q, KA, nullptr, scores, SEQ, SEQ, DIM, sQK, sQK, sS, scale);
    softmax_kernel<<<ROWS, blk>>>(scores);
    mma_gemm<false,false,false><<<gAV, blk, SMEM_BYTES>>>(scores, VA, nullptr, interp, SEQ, DIM, SEQ, sS, sQK, sQK, 1.0f);

    // attention B (accumulate)
    mma_gemm<true,false,false><<<gScore, blk, SMEM_BYTES>>>(Q, KB, nullptr, scores, SEQ, SEQ, DIM, sQK, sQK, sS, scale);
    softmax_kernel<<<ROWS, blk>>>(scores);
    mma_gemm<false,true,false><<<gAV, blk, SMEM_BYTES>>>(scores, VB, nullptr, interp, SEQ, DIM, SEQ, sS, sQK, sQK, 1.0f);

    // residual + LN, then FC
    ln_kernel<<<ROWS, blk>>>(interp, xC, gamma, beta, h);
    mma_gemm<true,false,true><<<gProj, blk, SMEM_BYTES>>>(h, Wfc, bfc, out, ROWS, DIM, DIM, 0,0,0, 1.0f);
}

// round 8
// speedup vs baseline: 3.1344x; 1.0495x over previous
#include <cuda_runtime.h>
#include <math.h>
#include <stdint.h>

#define DIM 768
#define BATCH 16
#define SEQ 1024
#define ROWS (BATCH*SEQ)   // 16384

// ---------------- scratch (module-load allocation, legal) ----------------
__device__ float g_xA[(size_t)ROWS*DIM];
__device__ float g_xB[(size_t)ROWS*DIM];
__device__ float g_xC[(size_t)ROWS*DIM];
__device__ float g_Wq[(size_t)DIM*DIM];
__device__ float g_Wk[(size_t)DIM*DIM];
__device__ float g_Wv[(size_t)DIM*DIM];
__device__ float g_Wfc[(size_t)DIM*DIM];
__device__ float g_Q[(size_t)ROWS*DIM];
__device__ float g_KA[(size_t)ROWS*DIM];
__device__ float g_KB[(size_t)ROWS*DIM];
__device__ float g_VA[(size_t)ROWS*DIM];
__device__ float g_VB[(size_t)ROWS*DIM];
__device__ float g_interp[(size_t)ROWS*DIM];
__device__ float g_h[(size_t)ROWS*DIM];
__device__ float g_scores[(size_t)BATCH*SEQ*SEQ];

// ---------------- helpers ----------------
__device__ __forceinline__ uint32_t f2tf(float x) {
    uint32_t u;
    asm("cvt.rna.tf32.f32 %0, %1;" : "=r"(u) : "f"(x));
    return u;
}
__device__ __forceinline__ float f2tf_f(float x) { return __uint_as_float(f2tf(x)); }

__device__ __forceinline__ void cp16(uint32_t d, const float* s) {
    asm volatile("cp.async.ca.shared.global [%0], [%1], 16;" :: "r"(d), "l"(s));
}
__device__ __forceinline__ void cpcommit() { asm volatile("cp.async.commit_group;"); }

__device__ __forceinline__ void mma_tf32(float* c, const uint32_t* a, const uint32_t* b) {
    asm("mma.sync.aligned.m16n8k8.row.col.f32.tf32.tf32.f32 "
        "{%0,%1,%2,%3}, {%4,%5,%6,%7}, {%8,%9}, {%0,%1,%2,%3};"
        : "+f"(c[0]), "+f"(c[1]), "+f"(c[2]), "+f"(c[3])
        : "r"(a[0]), "r"(a[1]), "r"(a[2]), "r"(a[3]), "r"(b[0]), "r"(b[1]));
}

// ---------------- tf32 tensor-core GEMM (mma.sync) ----------------
// C = alpha * A @ op(B) (+bias) (+C).  A:[M,K] row-major, PRE-ROUNDED to tf32.
// TRANS_B: B:[N,K] row-major (C=A*B^T).  !TRANS_B: B:[K,N] row-major.
constexpr int BM = 128, BN = 128, BK = 32;
constexpr int LDS_A = BK + 4;                 // 36 floats: A/B-trans row stride
constexpr int LDS_BN = BN + 4;                // 132 floats: B-notrans row stride
constexpr int ASZ = BM * LDS_A;               // 4608 floats
constexpr int BSZ = BM * LDS_A;               // max(128*36, 32*132)=4608
constexpr int STAGEF = ASZ + BSZ;
constexpr int SMEM_BYTES = 2 * STAGEF * 4;    // 73728 bytes

template<bool TRANS_B, bool ADD_C, bool HAS_BIAS, bool ROUND_OUT>
__global__ __launch_bounds__(256)
void mma_gemm(const float* __restrict__ Ag, const float* __restrict__ Bg,
              const float* __restrict__ bias, float* __restrict__ Cg,
              int M, int N, int K, long sA, long sB, long sC, float alpha)
{
    extern __shared__ float sm[];
    const float* A = Ag + (size_t)blockIdx.z * sA;
    const float* B = Bg + (size_t)blockIdx.z * sB;
    float*       C = Cg + (size_t)blockIdx.z * sC;

    const int t    = threadIdx.x;
    const int lane = t & 31;
    const int warp = t >> 5;
    const int wm   = warp >> 1;      // 0..3
    const int wn   = warp & 1;       // 0..1
    const int g    = lane >> 2;      // 0..7
    const int c    = lane & 3;       // 0..3
    const int m0   = blockIdx.y * BM;
    const int n0   = blockIdx.x * BN;

    const uint32_t smBase = (uint32_t)__cvta_generic_to_shared(sm);

    float acc[2][8][4] = {};
    const int nkt = K / BK;

    auto issue = [&](int kt, int st) {
        const float* Ab = A + (size_t)m0 * K + kt * BK;
        uint32_t as = smBase + st * STAGEF * 4;
        #pragma unroll
        for (int i = 0; i < 4; i++) {
            int idx = t + 256 * i;
            int r = idx >> 3, q = idx & 7;
            cp16(as + (uint32_t)(r * LDS_A + q * 4) * 4, Ab + (size_t)r * K + q * 4);
        }
        uint32_t bs = smBase + (st * STAGEF + ASZ) * 4;
        if (TRANS_B) {
            const float* Bb = B + (size_t)n0 * K + kt * BK;
            #pragma unroll
            for (int i = 0; i < 4; i++) {
                int idx = t + 256 * i;
                int r = idx >> 3, q = idx & 7;
                cp16(bs + (uint32_t)(r * LDS_A + q * 4) * 4, Bb + (size_t)r * K + q * 4);
            }
        } else {
            const float* Bb = B + (size_t)(kt * BK) * N + n0;
            #pragma unroll
            for (int i = 0; i < 4; i++) {
                int idx = t + 256 * i;
                int k = idx >> 5, nq = idx & 31;
                cp16(bs + (uint32_t)(k * LDS_BN + nq * 4) * 4, Bb + (size_t)k * N + nq * 4);
            }
        }
        cpcommit();
    };

    issue(0, 0);
    int st = 0;
    for (int kt = 0; kt < nkt; kt++) {
        if (kt + 1 < nkt) {
            issue(kt + 1, st ^ 1);
            asm volatile("cp.async.wait_group 1;");
        } else {
            asm volatile("cp.async.wait_group 0;");
        }
        __syncthreads();

        const uint32_t* As = reinterpret_cast<const uint32_t*>(sm + st * STAGEF);
        const uint32_t* Bs = As + ASZ;
        const uint32_t* aP = As + (wm * 32 + g) * LDS_A + c;

        #pragma unroll
        for (int ks = 0; ks < 4; ks++) {
            uint32_t af[2][4];
            #pragma unroll
            for (int mi = 0; mi < 2; mi++) {
                const uint32_t* p = aP + mi * 16 * LDS_A + ks * 8;
                af[mi][0] = p[0];
                af[mi][1] = p[8 * LDS_A];
                af[mi][2] = p[4];
                af[mi][3] = p[8 * LDS_A + 4];
            }
            uint32_t bf[8][2];
            if (TRANS_B) {
                const uint32_t* bP = Bs + (wn * 64 + g) * LDS_A + c + ks * 8;
                #pragma unroll
                for (int ni = 0; ni < 8; ni++) {
                    bf[ni][0] = bP[ni * 8 * LDS_A];
                    bf[ni][1] = bP[ni * 8 * LDS_A + 4];
                }
            } else {
                const uint32_t* bP = Bs + (ks * 8 + c) * LDS_BN + wn * 64 + g;
                #pragma unroll
                for (int ni = 0; ni < 8; ni++) {
                    bf[ni][0] = bP[ni * 8];
                    bf[ni][1] = bP[4 * LDS_BN + ni * 8];
                }
            }
            #pragma unroll
            for (int mi = 0; mi < 2; mi++)
                #pragma unroll
                for (int ni = 0; ni < 8; ni++)
                    mma_tf32(acc[mi][ni], af[mi], bf[ni]);
        }
        __syncthreads();
        st ^= 1;
    }

    // epilogue
    #pragma unroll
    for (int mi = 0; mi < 2; mi++) {
        int r0 = m0 + wm * 32 + mi * 16 + g;
        int r1 = r0 + 8;
        #pragma unroll
        for (int ni = 0; ni < 8; ni++) {
            int col = n0 + wn * 64 + ni * 8 + 2 * c;
            float2 v0, v1;
            v0.x = alpha * acc[mi][ni][0];
            v0.y = alpha * acc[mi][ni][1];
            v1.x = alpha * acc[mi][ni][2];
            v1.y = alpha * acc[mi][ni][3];
            if (HAS_BIAS) {
                float bx = bias[col], by = bias[col + 1];
                v0.x += bx; v0.y += by;
                v1.x += bx; v1.y += by;
            }
            float* p0 = &C[(size_t)r0 * N + col];
            float* p1 = &C[(size_t)r1 * N + col];
            if (ADD_C) {
                float2 o0 = *reinterpret_cast<const float2*>(p0);
                float2 o1 = *reinterpret_cast<const float2*>(p1);
                v0.x += o0.x; v0.y += o0.y;
                v1.x += o1.x; v1.y += o1.y;
            }
            if (ROUND_OUT) {
                v0.x = f2tf_f(v0.x); v0.y = f2tf_f(v0.y);
                v1.x = f2tf_f(v1.x); v1.y = f2tf_f(v1.y);
            }
            *reinterpret_cast<float2*>(p0) = v0;
            *reinterpret_cast<float2*>(p1) = v1;
        }
    }
}

// ---------------- elementwise tf32 pre-round (RNA) ----------------
__global__ __launch_bounds__(256)
void round_kernel(const float* __restrict__ src, float* __restrict__ dst, int n4)
{
    int i = blockIdx.x * blockDim.x + threadIdx.x;
    if (i < n4) {
        float4 v = reinterpret_cast<const float4*>(src)[i];
        v.x = f2tf_f(v.x); v.y = f2tf_f(v.y); v.z = f2tf_f(v.z); v.w = f2tf_f(v.w);
        reinterpret_cast<float4*>(dst)[i] = v;
    }
}

// ---------------- row softmax over SEQ=1024 (+tf32 round) ----------------
__global__ __launch_bounds__(256)
void softmax_kernel(float* __restrict__ S)
{
    __shared__ float sh[8];
    float* p = S + (size_t)blockIdx.x * SEQ;
    const int t = threadIdx.x;
    float4 v = reinterpret_cast<float4*>(p)[t];

    float m = fmaxf(fmaxf(v.x, v.y), fmaxf(v.z, v.w));
    #pragma unroll
    for (int o = 16; o > 0; o >>= 1) m = fmaxf(m, __shfl_xor_sync(0xffffffffu, m, o));
    if ((t & 31) == 0) sh[t >> 5] = m;
    __syncthreads();
    m = sh[0];
    #pragma unroll
    for (int i = 1; i < 8; i++) m = fmaxf(m, sh[i]);
    __syncthreads();

    v.x = expf(v.x - m); v.y = expf(v.y - m);
    v.z = expf(v.z - m); v.w = expf(v.w - m);
    float s = v.x + v.y + v.z + v.w;
    #pragma unroll
    for (int o = 16; o > 0; o >>= 1) s += __shfl_xor_sync(0xffffffffu, s, o);
    if ((t & 31) == 0) sh[t >> 5] = s;
    __syncthreads();
    s = sh[0];
    #pragma unroll
    for (int i = 1; i < 8; i++) s += sh[i];

    float inv = 1.0f / s;
    v.x = f2tf_f(v.x * inv); v.y = f2tf_f(v.y * inv);
    v.z = f2tf_f(v.z * inv); v.w = f2tf_f(v.w * inv);
    reinterpret_cast<float4*>(p)[t] = v;
}

// ------------- fused residual-add + LayerNorm over DIM=768 (+tf32 round) -------------
__global__ __launch_bounds__(256)
void ln_kernel(const float* __restrict__ interp, const float* __restrict__ xC,
               const float* __restrict__ gamma, const float* __restrict__ beta,
               float* __restrict__ H)
{
    __shared__ float sh[8];
    const size_t row = blockIdx.x;
    const float* a = interp + row * DIM;
    const float* c = xC + row * DIM;
    const int t = threadIdx.x;

    float x0 = a[t]       + c[t];
    float x1 = a[t + 256] + c[t + 256];
    float x2 = a[t + 512] + c[t + 512];

    float s = x0 + x1 + x2;
    #pragma unroll
    for (int o = 16; o > 0; o >>= 1) s += __shfl_xor_sync(0xffffffffu, s, o);
    if ((t & 31) == 0) sh[t >> 5] = s;
    __syncthreads();
    s = sh[0];
    #pragma unroll
    for (int i = 1; i < 8; i++) s += sh[i];
    const float mu = s * (1.0f / DIM);
    __syncthreads();

    float d0 = x0 - mu, d1 = x1 - mu, d2 = x2 - mu;
    float q = d0*d0 + d1*d1 + d2*d2;
    #pragma unroll
    for (int o = 16; o > 0; o >>= 1) q += __shfl_xor_sync(0xffffffffu, q, o);
    if ((t & 31) == 0) sh[t >> 5] = q;
    __syncthreads();
    q = sh[0];
    #pragma unroll
    for (int i = 1; i < 8; i++) q += sh[i];

    const float rstd = rsqrtf(q * (1.0f / DIM) + 1e-5f);
    float* hp = H + row * DIM;
    hp[t]       = f2tf_f(d0 * rstd * gamma[t]       + beta[t]);
    hp[t + 256] = f2tf_f(d1 * rstd * gamma[t + 256] + beta[t + 256]);
    hp[t + 512] = f2tf_f(d2 * rstd * gamma[t + 512] + beta[t + 512]);
}

// ---------------------------------- launch ----------------------------------
extern "C" void kernel_launch(void* const* d_in, const int* in_sizes, int n_in,
                              void* d_out, int out_size)
{
    const float* xA    = (const float*)d_in[0];
    const float* xB    = (const float*)d_in[1];
    const float* xC    = (const float*)d_in[2];
    const float* Wq    = (const float*)d_in[3];
    const float* bq    = (const float*)d_in[4];
    const float* Wk    = (const float*)d_in[5];
    const float* bk    = (const float*)d_in[6];
    const float* Wv    = (const float*)d_in[7];
    const float* bv    = (const float*)d_in[8];
    const float* gamma = (const float*)d_in[9];
    const float* beta  = (const float*)d_in[10];
    const float* Wfc   = (const float*)d_in[11];
    const float* bfc   = (const float*)d_in[12];
    float* out = (float*)d_out;

    float *rxA, *rxB, *rxC, *rWq, *rWk, *rWv, *rWfc;
    float *Q, *KA, *KB, *VA, *VB, *interp, *h, *scores;
    cudaGetSymbolAddress((void**)&rxA,  g_xA);
    cudaGetSymbolAddress((void**)&rxB,  g_xB);
    cudaGetSymbolAddress((void**)&rxC,  g_xC);
    cudaGetSymbolAddress((void**)&rWq,  g_Wq);
    cudaGetSymbolAddress((void**)&rWk,  g_Wk);
    cudaGetSymbolAddress((void**)&rWv,  g_Wv);
    cudaGetSymbolAddress((void**)&rWfc, g_Wfc);
    cudaGetSymbolAddress((void**)&Q,      g_Q);
    cudaGetSymbolAddress((void**)&KA,     g_KA);
    cudaGetSymbolAddress((void**)&KB,     g_KB);
    cudaGetSymbolAddress((void**)&VA,     g_VA);
    cudaGetSymbolAddress((void**)&VB,     g_VB);
    cudaGetSymbolAddress((void**)&interp, g_interp);
    cudaGetSymbolAddress((void**)&h,      g_h);
    cudaGetSymbolAddress((void**)&scores, g_scores);

    cudaFuncSetAttribute(mma_gemm<true,  false, true,  true >, cudaFuncAttributeMaxDynamicSharedMemorySize, SMEM_BYTES);
    cudaFuncSetAttribute(mma_gemm<true,  false, false, false>, cudaFuncAttributeMaxDynamicSharedMemorySize, SMEM_BYTES);
    cudaFuncSetAttribute(mma_gemm<false, false, false, false>, cudaFuncAttributeMaxDynamicSharedMemorySize, SMEM_BYTES);
    cudaFuncSetAttribute(mma_gemm<false, true,  false, false>, cudaFuncAttributeMaxDynamicSharedMemorySize, SMEM_BYTES);
    cudaFuncSetAttribute(mma_gemm<true,  false, true,  false>, cudaFuncAttributeMaxDynamicSharedMemorySize, SMEM_BYTES);

    const dim3 blk(256);
    const dim3 gProj(DIM / BN, ROWS / BM, 1);      // (6,128)
    const dim3 gScore(SEQ / BN, SEQ / BM, BATCH);  // (8,8,16)
    const dim3 gAV(DIM / BN, SEQ / BM, BATCH);     // (6,8,16)
    const long sQK = (long)SEQ * DIM;
    const long sS  = (long)SEQ * SEQ;
    const float scale = 1.0f / sqrtf((float)DIM);

    // tf32 pre-round (RNA) of all GEMM LHS/RHS operands
    const int nx4 = ROWS * DIM / 4, nw4 = DIM * DIM / 4;
    round_kernel<<<(nx4 + 255) / 256, 256>>>(xA, rxA, nx4);
    round_kernel<<<(nx4 + 255) / 256, 256>>>(xB, rxB, nx4);
    round_kernel<<<(nx4 + 255) / 256, 256>>>(xC, rxC, nx4);
    round_kernel<<<(nw4 + 255) / 256, 256>>>(Wq,  rWq,  nw4);
    round_kernel<<<(nw4 + 255) / 256, 256>>>(Wk,  rWk,  nw4);
    round_kernel<<<(nw4 + 255) / 256, 256>>>(Wv,  rWv,  nw4);
    round_kernel<<<(nw4 + 255) / 256, 256>>>(Wfc, rWfc, nw4);

    // projections (epilogue rounds Q/K/V to tf32 for downstream GEMMs)
    mma_gemm<true,false,true,true><<<gProj, blk, SMEM_BYTES>>>(rxC, rWq, bq, Q,  ROWS, DIM, DIM, 0,0,0, 1.0f);
    mma_gemm<true,false,true,true><<<gProj, blk, SMEM_BYTES>>>(rxA, rWk, bk, KA, ROWS, DIM, DIM, 0,0,0, 1.0f);
    mma_gemm<true,false,true,true><<<gProj, blk, SMEM_BYTES>>>(rxB, rWk, bk, KB, ROWS, DIM, DIM, 0,0,0, 1.0f);
    mma_gemm<true,false,true,true><<<gProj, blk, SMEM_BYTES>>>(rxA, rWv, bv, VA, ROWS, DIM, DIM, 0,0,0, 1.0f);
    mma_gemm<true,false,true,true><<<gProj, blk, SMEM_BYTES>>>(rxB, rWv, bv, VB, ROWS, DIM, DIM, 0,0,0, 1.0f);

    // attention A
    mma_gemm<true,false,false,false><<<gScore, blk, SMEM_BYTES>>>(Q, KA, nullptr, scores, SEQ, SEQ, DIM, sQK, sQK, sS, scale);
    softmax_kernel<<<ROWS, blk>>>(scores);
    mma_gemm<false,false,false,false><<<gAV, blk, SMEM_BYTES>>>(scores, VA, nullptr, interp, SEQ, DIM, SEQ, sS, sQK, sQK, 1.0f);

    // attention B (accumulate)
    mma_gemm<true,false,false,false><<<gScore, blk, SMEM_BYTES>>>(Q, KB, nullptr, scores, SEQ, SEQ, DIM, sQK, sQK, sS, scale);
    softmax_kernel<<<ROWS, blk>>>(scores);
    mma_gemm<false,true,false,false><<<gAV, blk, SMEM_BYTES>>>(scores, VB, nullptr, interp, SEQ, DIM, SEQ, sS, sQK, sQK, 1.0f);

    // residual + LN (rounds h), then FC (fp32 out)
    ln_kernel<<<ROWS, blk>>>(interp, rxC, gamma, beta, h);
    mma_gemm<true,false,true,false><<<gProj, blk, SMEM_BYTES>>>(h, rWfc, bfc, out, ROWS, DIM, DIM, 0,0,0, 1.0f);
}

// round 9
// speedup vs baseline: 3.7175x; 1.1860x over previous
#include <cuda_runtime.h>
#include <math.h>
#include <stdint.h>

#define DIM 768
#define BATCH 16
#define SEQ 1024
#define ROWS (BATCH*SEQ)   // 16384

// ---------------- scratch (module-load allocation, legal) ----------------
__device__ float g_xA[(size_t)ROWS*DIM];      // A_perm
__device__ float g_xB[(size_t)ROWS*DIM];      // A_perm
__device__ float g_xC[(size_t)ROWS*DIM];      // A_perm
__device__ float g_Wq[(size_t)DIM*DIM];       // B_perm
__device__ float g_Wk[(size_t)DIM*DIM];       // B_perm
__device__ float g_Wv[(size_t)DIM*DIM];       // B_perm
__device__ float g_Wfc[(size_t)DIM*DIM];      // B_perm
__device__ float g_Q[(size_t)ROWS*DIM];       // A_perm
__device__ float g_KA[(size_t)ROWS*DIM];      // B_perm  [seq,dim]
__device__ float g_KB[(size_t)ROWS*DIM];      // B_perm
__device__ float g_VA[(size_t)ROWS*DIM];      // B_perm  [dim,seq] per batch
__device__ float g_VB[(size_t)ROWS*DIM];      // B_perm
__device__ float g_interp[(size_t)ROWS*DIM];  // normal
__device__ float g_h[(size_t)ROWS*DIM];       // A_perm
__device__ float g_scores[(size_t)BATCH*SEQ*SEQ]; // A_perm per batch

// ---------------- helpers ----------------
__device__ __forceinline__ uint32_t f2tf(float x) {
    uint32_t u;
    asm("cvt.rna.tf32.f32 %0, %1;" : "=r"(u) : "f"(x));
    return u;
}
__device__ __forceinline__ float f2tf_f(float x) { return __uint_as_float(f2tf(x)); }

__device__ __forceinline__ void cp16(uint32_t d, const float* s) {
    asm volatile("cp.async.ca.shared.global [%0], [%1], 16;" :: "r"(d), "l"(s));
}
__device__ __forceinline__ void cpcommit() { asm volatile("cp.async.commit_group;"); }

__device__ __forceinline__ void mma_tf32(float* c, const uint32_t* a, const uint32_t* b) {
    asm("mma.sync.aligned.m16n8k8.row.col.f32.tf32.tf32.f32 "
        "{%0,%1,%2,%3}, {%4,%5,%6,%7}, {%8,%9}, {%0,%1,%2,%3};"
        : "+f"(c[0]), "+f"(c[1]), "+f"(c[2]), "+f"(c[3])
        : "r"(a[0]), "r"(a[1]), "r"(a[2]), "r"(a[3]), "r"(b[0]), "r"(b[1]));
}

// Fragment-major layouts:
// A_perm: 16m x 8k blocks (512B). lane l=(g=l>>2, c=l&3) holds 16B:
//   { A[g][c], A[g+8][c], A[g][c+4], A[g+8][c+4] }  (exact m16n8k8 A fragment)
// B_perm: 8n x 8k blocks (256B). lane l holds 8B:
//   { B[g][c], B[g][c+4] }                           (exact B fragment)

// ---------------- prepass: round + pack ----------------
__global__ __launch_bounds__(256)
void pack_A(const float* __restrict__ src, float* __restrict__ dst, int R, int K)
{
    int warpg = blockIdx.x * 8 + (threadIdx.x >> 5);
    int nblk = (R >> 4) * (K >> 3);
    if (warpg >= nblk) return;
    int K8 = K >> 3;
    int mb = warpg / K8, kb = warpg % K8;
    int lane = threadIdx.x & 31;
    int g = lane >> 2, c = lane & 3;
    const float* s = src + (size_t)(mb * 16 + g) * K + kb * 8 + c;
    float4 v;
    v.x = f2tf_f(s[0]);
    v.y = f2tf_f(s[(size_t)8 * K]);
    v.z = f2tf_f(s[4]);
    v.w = f2tf_f(s[(size_t)8 * K + 4]);
    *reinterpret_cast<float4*>(dst + (size_t)warpg * 128 + lane * 4) = v;
}

__global__ __launch_bounds__(256)
void pack_B(const float* __restrict__ src, float* __restrict__ dst, int N, int K)
{
    int u = blockIdx.x * 256 + threadIdx.x;
    int total = (N * K) >> 1;
    if (u >= total) return;
    int blk = u >> 5, lane = u & 31;
    int K8 = K >> 3;
    int nb = blk / K8, kb = blk % K8;
    int g = lane >> 2, c = lane & 3;
    const float* s = src + (size_t)(nb * 8 + g) * K + kb * 8 + c;
    float2 v;
    v.x = f2tf_f(s[0]);
    v.y = f2tf_f(s[4]);
    *reinterpret_cast<float2*>(dst + (size_t)u * 2) = v;
}

// ---------------- tf32 GEMM on fragment-major operands ----------------
// C = alpha * A @ B^T (+bias) (+C). A: A_perm [M,K]; B: B_perm [N,K].
// WB: 0=normal row-major C; 1=A_perm(Kp); 2=B_perm(Kp); 3=B_perm transposed
//     (out[n=col][k=row%1024], batch=row/1024, per-batch stride sC).
constexpr int BM = 128, BN = 128, BK = 32;
constexpr int STAGE_BYTES = 32768;           // A 16KB + B 16KB
constexpr int SMEM_BYTES = 2 * STAGE_BYTES;  // 65536

template<int WB, bool ADD_C, bool HAS_BIAS, bool ROUND_OUT>
__global__ __launch_bounds__(256, 2)
void mma_gemm(const float* __restrict__ Ag, const float* __restrict__ Bg,
              const float* __restrict__ bias, float* __restrict__ Cg,
              int N, int K, int Kp, long sA, long sB, long sC, float alpha)
{
    extern __shared__ __align__(16) char smem[];
    const float* A = Ag + (size_t)blockIdx.z * sA;
    const float* B = Bg + (size_t)blockIdx.z * sB;

    const int t    = threadIdx.x;
    const int lane = t & 31;
    const int warp = t >> 5;
    const int wm   = warp >> 1;
    const int wn   = warp & 1;
    const int g    = lane >> 2;
    const int c    = lane & 3;
    const int m0   = blockIdx.y * BM;
    const int n0   = blockIdx.x * BN;

    const uint32_t smBase = (uint32_t)__cvta_generic_to_shared(smem);
    const int K8 = K >> 3;
    const float* Abase = A + (size_t)(m0 >> 4) * K8 * 128;
    const float* Bbase = B + (size_t)(n0 >> 3) * K8 * 64;

    float acc[2][8][4] = {};
    const int nkt = K / BK;

    auto issue = [&](int kt, int st) {
        uint32_t as = smBase + st * STAGE_BYTES;
        const float* Ab = Abase + (size_t)kt * 512;   // 4 blocks * 128 floats
        #pragma unroll
        for (int i = 0; i < 4; i++) {
            int idx = t + 256 * i;
            int mi_ = idx >> 7, rest = idx & 127;
            cp16(as + mi_ * 2048 + rest * 16, Ab + (size_t)mi_ * K8 * 128 + rest * 4);
        }
        uint32_t bs = as + 16384;
        const float* Bb = Bbase + (size_t)kt * 256;   // 4 blocks * 64 floats
        #pragma unroll
        for (int i = 0; i < 4; i++) {
            int idx = t + 256 * i;
            int ni_ = idx >> 6, rest = idx & 63;
            cp16(bs + ni_ * 1024 + rest * 16, Bb + (size_t)ni_ * K8 * 64 + rest * 4);
        }
        cpcommit();
    };

    issue(0, 0);
    int st = 0;
    for (int kt = 0; kt < nkt; kt++) {
        if (kt + 1 < nkt) {
            issue(kt + 1, st ^ 1);
            asm volatile("cp.async.wait_group 1;");
        } else {
            asm volatile("cp.async.wait_group 0;");
        }
        __syncthreads();

        const char* sAc = smem + st * STAGE_BYTES;
        const char* sBc = sAc + 16384;

        #pragma unroll
        for (int ks = 0; ks < 4; ks++) {
            uint4 af[2];
            #pragma unroll
            for (int mi = 0; mi < 2; mi++)
                af[mi] = *reinterpret_cast<const uint4*>(
                    sAc + ((wm * 2 + mi) * 4 + ks) * 512 + lane * 16);
            uint2 bf[8];
            #pragma unroll
            for (int ni = 0; ni < 8; ni++)
                bf[ni] = *reinterpret_cast<const uint2*>(
                    sBc + ((wn * 8 + ni) * 4 + ks) * 256 + lane * 8);
            #pragma unroll
            for (int mi = 0; mi < 2; mi++)
                #pragma unroll
                for (int ni = 0; ni < 8; ni++)
                    mma_tf32(acc[mi][ni],
                             reinterpret_cast<const uint32_t*>(&af[mi]),
                             reinterpret_cast<const uint32_t*>(&bf[ni]));
        }
        __syncthreads();
        st ^= 1;
    }

    // ---------------- epilogue ----------------
    #pragma unroll
    for (int mi = 0; mi < 2; mi++) {
        const int r0 = m0 + wm * 32 + mi * 16 + g;
        #pragma unroll
        for (int ni = 0; ni < 8; ni++) {
            const int col = n0 + wn * 64 + ni * 8 + 2 * c;
            float v0 = alpha * acc[mi][ni][0];
            float v1 = alpha * acc[mi][ni][1];
            float v2 = alpha * acc[mi][ni][2];
            float v3 = alpha * acc[mi][ni][3];
            if (HAS_BIAS) {
                float bx = bias[col], by = bias[col + 1];
                v0 += bx; v1 += by; v2 += bx; v3 += by;
            }
            if (WB == 0) {
                float* p0 = Cg + (size_t)blockIdx.z * sC + (size_t)r0 * N + col;
                float* p1 = p0 + (size_t)8 * N;
                float2 a0, a1;
                a0.x = v0; a0.y = v1; a1.x = v2; a1.y = v3;
                if (ADD_C) {
                    float2 o0 = *reinterpret_cast<const float2*>(p0);
                    float2 o1 = *reinterpret_cast<const float2*>(p1);
                    a0.x += o0.x; a0.y += o0.y; a1.x += o1.x; a1.y += o1.y;
                }
                if (ROUND_OUT) {
                    a0.x = f2tf_f(a0.x); a0.y = f2tf_f(a0.y);
                    a1.x = f2tf_f(a1.x); a1.y = f2tf_f(a1.y);
                }
                *reinterpret_cast<float2*>(p0) = a0;
                *reinterpret_cast<float2*>(p1) = a1;
            } else if (WB == 1) {
                if (ROUND_OUT) { v0 = f2tf_f(v0); v1 = f2tf_f(v1); v2 = f2tf_f(v2); v3 = f2tf_f(v3); }
                float* base = Cg + (size_t)blockIdx.z * sC;
                size_t off = ((size_t)(r0 >> 4) * (Kp >> 3) + (col >> 3)) * 128
                           + (size_t)(((r0 & 7) * 4 + (col & 3)) * 4 + 2 * ((col >> 2) & 1));
                float2 a0, a1;
                a0.x = v0; a0.y = v2;    // (r0, col), (r0+8, col)
                a1.x = v1; a1.y = v3;    // (r0, col+1), (r0+8, col+1)
                *reinterpret_cast<float2*>(base + off) = a0;
                *reinterpret_cast<float2*>(base + off + 4) = a1;
            } else if (WB == 2) {
                if (ROUND_OUT) { v0 = f2tf_f(v0); v1 = f2tf_f(v1); v2 = f2tf_f(v2); v3 = f2tf_f(v3); }
                float* base = Cg + (size_t)blockIdx.z * sC;
                #pragma unroll
                for (int e = 0; e < 4; e++) {
                    int r = r0 + (e >> 1) * 8;
                    int k = col + (e & 1);
                    float vv = (e == 0) ? v0 : (e == 1) ? v1 : (e == 2) ? v2 : v3;
                    size_t off = ((size_t)(r >> 3) * (Kp >> 3) + (k >> 3)) * 64
                               + (size_t)(((r & 7) * 4 + (k & 3)) * 2 + ((k >> 2) & 1));
                    base[off] = vv;
                }
            } else {  // WB == 3
                if (ROUND_OUT) { v0 = f2tf_f(v0); v1 = f2tf_f(v1); v2 = f2tf_f(v2); v3 = f2tf_f(v3); }
                int b = r0 >> 10;
                float* base = Cg + (size_t)b * sC;
                #pragma unroll
                for (int e = 0; e < 4; e++) {
                    int rl = (r0 & 1023) + (e >> 1) * 8;
                    int n = col + (e & 1);
                    float vv = (e == 0) ? v0 : (e == 1) ? v1 : (e == 2) ? v2 : v3;
                    size_t off = ((size_t)(n >> 3) * (Kp >> 3) + (rl >> 3)) * 64
                               + (size_t)(((n & 7) * 4 + (rl & 3)) * 2 + ((rl >> 2) & 1));
                    base[off] = vv;
                }
            }
        }
    }
}

// ---------------- softmax on A_perm scores: one block per row-pair (m, m+8) ----------------
__global__ __launch_bounds__(256)
void softmax_perm(float* __restrict__ S)
{
    __shared__ float sh0[8], sh1[8];
    const int bid = blockIdx.x;
    const int g = bid & 7, mh = (bid >> 3) & 63, b = bid >> 9;
    float* base = S + (size_t)b * SEQ * SEQ + (size_t)mh * 16384 + g * 16;
    const int t = threadIdx.x;
    const int lane = t & 31, wid = t >> 5;
    const int j = t & 3, kh = t >> 2;   // kh 0..63

    float* p0 = base + (size_t)kh * 128 + j * 4;
    float* p1 = base + (size_t)(kh + 64) * 128 + j * 4;
    float4 u0 = *reinterpret_cast<float4*>(p0);
    float4 u1 = *reinterpret_cast<float4*>(p1);
    // x,z -> row m ; y,w -> row m+8

    float m0v = fmaxf(fmaxf(u0.x, u0.z), fmaxf(u1.x, u1.z));
    float m1v = fmaxf(fmaxf(u0.y, u0.w), fmaxf(u1.y, u1.w));
    #pragma unroll
    for (int o = 16; o > 0; o >>= 1) {
        m0v = fmaxf(m0v, __shfl_xor_sync(0xffffffffu, m0v, o));
        m1v = fmaxf(m1v, __shfl_xor_sync(0xffffffffu, m1v, o));
    }
    if (lane == 0) { sh0[wid] = m0v; sh1[wid] = m1v; }
    __syncthreads();
    m0v = sh0[0]; m1v = sh1[0];
    #pragma unroll
    for (int i = 1; i < 8; i++) { m0v = fmaxf(m0v, sh0[i]); m1v = fmaxf(m1v, sh1[i]); }
    __syncthreads();

    u0.x = expf(u0.x - m0v); u0.z = expf(u0.z - m0v);
    u1.x = expf(u1.x - m0v); u1.z = expf(u1.z - m0v);
    u0.y = expf(u0.y - m1v); u0.w = expf(u0.w - m1v);
    u1.y = expf(u1.y - m1v); u1.w = expf(u1.w - m1v);

    float s0 = u0.x + u0.z + u1.x + u1.z;
    float s1 = u0.y + u0.w + u1.y + u1.w;
    #pragma unroll
    for (int o = 16; o > 0; o >>= 1) {
        s0 += __shfl_xor_sync(0xffffffffu, s0, o);
        s1 += __shfl_xor_sync(0xffffffffu, s1, o);
    }
    if (lane == 0) { sh0[wid] = s0; sh1[wid] = s1; }
    __syncthreads();
    s0 = sh0[0]; s1 = sh1[0];
    #pragma unroll
    for (int i = 1; i < 8; i++) { s0 += sh0[i]; s1 += sh1[i]; }

    const float i0 = 1.0f / s0, i1 = 1.0f / s1;
    u0.x = f2tf_f(u0.x * i0); u0.z = f2tf_f(u0.z * i0);
    u1.x = f2tf_f(u1.x * i0); u1.z = f2tf_f(u1.z * i0);
    u0.y = f2tf_f(u0.y * i1); u0.w = f2tf_f(u0.w * i1);
    u1.y = f2tf_f(u1.y * i1); u1.w = f2tf_f(u1.w * i1);
    *reinterpret_cast<float4*>(p0) = u0;
    *reinterpret_cast<float4*>(p1) = u1;
}

// ------------- fused residual-add + LayerNorm; writes h in A_perm (rounded) -------------
__global__ __launch_bounds__(256)
void ln_kernel(const float* __restrict__ interp, const float* __restrict__ xC,
               const float* __restrict__ gamma, const float* __restrict__ beta,
               float* __restrict__ H)
{
    __shared__ float sh[8];
    const size_t row = blockIdx.x;
    const float* a = interp + row * DIM;
    const float* cc = xC + row * DIM;
    const int t = threadIdx.x;

    float x0 = a[t]       + cc[t];
    float x1 = a[t + 256] + cc[t + 256];
    float x2 = a[t + 512] + cc[t + 512];

    float s = x0 + x1 + x2;
    #pragma unroll
    for (int o = 16; o > 0; o >>= 1) s += __shfl_xor_sync(0xffffffffu, s, o);
    if ((t & 31) == 0) sh[t >> 5] = s;
    __syncthreads();
    s = sh[0];
    #pragma unroll
    for (int i = 1; i < 8; i++) s += sh[i];
    const float mu = s * (1.0f / DIM);
    __syncthreads();

    float d0 = x0 - mu, d1 = x1 - mu, d2 = x2 - mu;
    float q = d0 * d0 + d1 * d1 + d2 * d2;
    #pragma unroll
    for (int o = 16; o > 0; o >>= 1) q += __shfl_xor_sync(0xffffffffu, q, o);
    if ((t & 31) == 0) sh[t >> 5] = q;
    __syncthreads();
    q = sh[0];
    #pragma unroll
    for (int i = 1; i < 8; i++) q += sh[i];

    const float rstd = rsqrtf(q * (1.0f / DIM) + 1e-5f);
    const int m = (int)row;
    const size_t rowblk = (size_t)(m >> 4) * (DIM >> 3);
    const int lanebase = (m & 7) * 4;
    const int sm = (m >> 3) & 1;
    #pragma unroll
    for (int i = 0; i < 3; i++) {
        int d = t + i * 256;
        float val = (i == 0 ? d0 : i == 1 ? d1 : d2) * rstd * gamma[d] + beta[d];
        size_t off = (rowblk + (d >> 3)) * 128
                   + (size_t)((lanebase + (d & 3)) * 4 + sm + 2 * ((d >> 2) & 1));
        H[off] = f2tf_f(val);
    }
}

// ---------------------------------- launch ----------------------------------
extern "C" void kernel_launch(void* const* d_in, const int* in_sizes, int n_in,
                              void* d_out, int out_size)
{
    const float* xA    = (const float*)d_in[0];
    const float* xB    = (const float*)d_in[1];
    const float* xC    = (const float*)d_in[2];
    const float* Wq    = (const float*)d_in[3];
    const float* bq    = (const float*)d_in[4];
    const float* Wk    = (const float*)d_in[5];
    const float* bk    = (const float*)d_in[6];
    const float* Wv    = (const float*)d_in[7];
    const float* bv    = (const float*)d_in[8];
    const float* gamma = (const float*)d_in[9];
    const float* beta  = (const float*)d_in[10];
    const float* Wfc   = (const float*)d_in[11];
    const float* bfc   = (const float*)d_in[12];
    float* out = (float*)d_out;

    float *pxA, *pxB, *pxC, *pWq, *pWk, *pWv, *pWfc;
    float *Q, *KA, *KB, *VA, *VB, *interp, *h, *scores;
    cudaGetSymbolAddress((void**)&pxA,  g_xA);
    cudaGetSymbolAddress((void**)&pxB,  g_xB);
    cudaGetSymbolAddress((void**)&pxC,  g_xC);
    cudaGetSymbolAddress((void**)&pWq,  g_Wq);
    cudaGetSymbolAddress((void**)&pWk,  g_Wk);
    cudaGetSymbolAddress((void**)&pWv,  g_Wv);
    cudaGetSymbolAddress((void**)&pWfc, g_Wfc);
    cudaGetSymbolAddress((void**)&Q,      g_Q);
    cudaGetSymbolAddress((void**)&KA,     g_KA);
    cudaGetSymbolAddress((void**)&KB,     g_KB);
    cudaGetSymbolAddress((void**)&VA,     g_VA);
    cudaGetSymbolAddress((void**)&VB,     g_VB);
    cudaGetSymbolAddress((void**)&interp, g_interp);
    cudaGetSymbolAddress((void**)&h,      g_h);
    cudaGetSymbolAddress((void**)&scores, g_scores);

    cudaFuncSetAttribute(mma_gemm<1, false, true,  true >, cudaFuncAttributeMaxDynamicSharedMemorySize, SMEM_BYTES);
    cudaFuncSetAttribute(mma_gemm<2, false, true,  true >, cudaFuncAttributeMaxDynamicSharedMemorySize, SMEM_BYTES);
    cudaFuncSetAttribute(mma_gemm<3, false, true,  true >, cudaFuncAttributeMaxDynamicSharedMemorySize, SMEM_BYTES);
    cudaFuncSetAttribute(mma_gemm<1, false, false, false>, cudaFuncAttributeMaxDynamicSharedMemorySize, SMEM_BYTES);
    cudaFuncSetAttribute(mma_gemm<0, false, false, false>, cudaFuncAttributeMaxDynamicSharedMemorySize, SMEM_BYTES);
    cudaFuncSetAttribute(mma_gemm<0, true,  false, false>, cudaFuncAttributeMaxDynamicSharedMemorySize, SMEM_BYTES);
    cudaFuncSetAttribute(mma_gemm<0, false, true,  false>, cudaFuncAttributeMaxDynamicSharedMemorySize, SMEM_BYTES);

    const long sQK = (long)SEQ * DIM;   // 786432
    const long sS  = (long)SEQ * SEQ;
    const float scale = 1.0f / sqrtf((float)DIM);

    // prepass: round + pack into fragment-major layouts
    {
        int nblkA = (ROWS >> 4) * (DIM >> 3);          // 98304
        pack_A<<<nblkA / 8, 256>>>(xA, pxA, ROWS, DIM);
        pack_A<<<nblkA / 8, 256>>>(xB, pxB, ROWS, DIM);
        pack_A<<<nblkA / 8, 256>>>(xC, pxC, ROWS, DIM);
        int nB = (DIM * DIM) >> 1;                     // 294912
        pack_B<<<nB / 256, 256>>>(Wq,  pWq,  DIM, DIM);
        pack_B<<<nB / 256, 256>>>(Wk,  pWk,  DIM, DIM);
        pack_B<<<nB / 256, 256>>>(Wv,  pWv,  DIM, DIM);
        pack_B<<<nB / 256, 256>>>(Wfc, pWfc, DIM, DIM);
    }

    const dim3 blk(256);
    const dim3 gProj(DIM / BN, ROWS / BM, 1);      // (6,128)
    const dim3 gScore(SEQ / BN, SEQ / BM, BATCH);  // (8,8,16)
    const dim3 gAV(DIM / BN, SEQ / BM, BATCH);     // (6,8,16)

    // projections: Q -> A_perm, K -> B_perm, V -> B_perm transposed; all rounded
    mma_gemm<1, false, true, true><<<gProj, blk, SMEM_BYTES>>>(pxC, pWq, bq, Q,  DIM, DIM, DIM, 0, 0, 0, 1.0f);
    mma_gemm<2, false, true, true><<<gProj, blk, SMEM_BYTES>>>(pxA, pWk, bk, KA, DIM, DIM, DIM, 0, 0, 0, 1.0f);
    mma_gemm<2, false, true, true><<<gProj, blk, SMEM_BYTES>>>(pxB, pWk, bk, KB, DIM, DIM, DIM, 0, 0, 0, 1.0f);
    mma_gemm<3, false, true, true><<<gProj, blk, SMEM_BYTES>>>(pxA, pWv, bv, VA, DIM, DIM, SEQ, 0, 0, sQK, 1.0f);
    mma_gemm<3, false, true, true><<<gProj, blk, SMEM_BYTES>>>(pxB, pWv, bv, VB, DIM, DIM, SEQ, 0, 0, sQK, 1.0f);

    // attention A: scores (A_perm) -> softmax -> PV (normal interp)
    mma_gemm<1, false, false, false><<<gScore, blk, SMEM_BYTES>>>(Q, KA, nullptr, scores, SEQ, DIM, SEQ, sQK, sQK, sS, scale);
    softmax_perm<<<BATCH * 512, 256>>>(scores);
    mma_gemm<0, false, false, false><<<gAV, blk, SMEM_BYTES>>>(scores, VA, nullptr, interp, DIM, SEQ, 0, sS, sQK, sQK, 1.0f);

    // attention B (accumulate into interp)
    mma_gemm<1, false, false, false><<<gScore, blk, SMEM_BYTES>>>(Q, KB, nullptr, scores, SEQ, DIM, SEQ, sQK, sQK, sS, scale);
    softmax_perm<<<BATCH * 512, 256>>>(scores);
    mma_gemm<0, true, false, false><<<gAV, blk, SMEM_BYTES>>>(scores, VB, nullptr, interp, DIM, SEQ, 0, sS, sQK, sQK, 1.0f);

    // residual + LN -> h (A_perm, rounded), then FC -> out (normal fp32)
    ln_kernel<<<ROWS, blk>>>(interp, xC, gamma, beta, h);
    mma_gemm<0, false, true, false><<<gProj, blk, SMEM_BYTES>>>(h, pWfc, bfc, out, DIM, DIM, 0, 0, 0, 0, 1.0f);
}